// round 8
// baseline (speedup 1.0000x reference)
#include <cuda_runtime.h>
#include <cstdint>

// ---------------- problem constants ----------------
#define NN 50000
#define EE 800000
#define GG 256
#define HH 64
#define INW 128
#define SCAN_BLK 512
#define NBLK ((NN + SCAN_BLK - 1) / SCAN_BLK)   // 98

// ---------------- device scratch (no allocation allowed) ----------------
__device__ float g_zl[NN * HH];
__device__ float g_zr[NN * HH];
__device__ float g_h[NN * HH];
__device__ int   g_cnt[NN];
__device__ int   g_offs[NN + 1];
__device__ int   g_cursor[NN];
__device__ int   g_csr[EE];
__device__ int   g_bsum[128];
__device__ float g_pool[GG * HH];
__device__ float g_pcnt[GG];
__device__ float g_cA[GG * 256];
__device__ float g_cB[GG * 256];

// ---------------- helpers ----------------
__device__ __forceinline__ void red_add_v4(float* a, float4 v) {
    asm volatile("red.global.add.v4.f32 [%0], {%1,%2,%3,%4};"
                 :: "l"(a), "f"(v.x), "f"(v.y), "f"(v.z), "f"(v.w) : "memory");
}
__device__ __forceinline__ void red_add_f(float* a, float v) {
    asm volatile("red.global.add.f32 [%0], %1;" :: "l"(a), "f"(v) : "memory");
}
// packed dual-fp32 FMA (FFMA2): d = a*b + d  (two lanes)
__device__ __forceinline__ void ffma2(unsigned long long& d,
                                      unsigned long long a, unsigned long long b) {
    asm("fma.rn.f32x2 %0, %1, %2, %0;" : "+l"(d) : "l"(a), "l"(b));
}
__device__ __forceinline__ unsigned long long pack2(float v) {
    unsigned long long r;
    asm("mov.b64 %0, {%1, %1};" : "=l"(r) : "f"(v));
    return r;
}

// ---------------- CSR build ----------------
__global__ void k_count(const int* __restrict__ dst, int* __restrict__ cnt, int E) {
    int e = blockIdx.x * blockDim.x + threadIdx.x;
    if (e >= E) return;
    unsigned d = (unsigned)dst[e];
    if (d < NN) atomicAdd(cnt + d, 1);
}

__global__ void k_scan1(const int* __restrict__ cnt, int* __restrict__ offs,
                        int* __restrict__ bsum, int N) {
    __shared__ int sh[SCAN_BLK];
    int i = blockIdx.x * SCAN_BLK + threadIdx.x;
    int v = (i < N) ? cnt[i] : 0;
    sh[threadIdx.x] = v;
    __syncthreads();
    for (int d = 1; d < SCAN_BLK; d <<= 1) {
        int t = (threadIdx.x >= d) ? sh[threadIdx.x - d] : 0;
        __syncthreads();
        sh[threadIdx.x] += t;
        __syncthreads();
    }
    if (i < N) offs[i] = sh[threadIdx.x] - v;   // exclusive
    if (threadIdx.x == SCAN_BLK - 1) bsum[blockIdx.x] = sh[SCAN_BLK - 1];
}

__global__ void k_scan2(int* __restrict__ bsum, int nb) {
    __shared__ int sh[128];
    int v = (threadIdx.x < nb) ? bsum[threadIdx.x] : 0;
    sh[threadIdx.x] = v;
    __syncthreads();
    for (int d = 1; d < 128; d <<= 1) {
        int t = (threadIdx.x >= d) ? sh[threadIdx.x - d] : 0;
        __syncthreads();
        sh[threadIdx.x] += t;
        __syncthreads();
    }
    if (threadIdx.x < nb) bsum[threadIdx.x] = sh[threadIdx.x] - v;   // exclusive
}

__global__ void k_scan3(int* __restrict__ offs, const int* __restrict__ bsum,
                        int* __restrict__ cursor, int N, int E) {
    int i = blockIdx.x * blockDim.x + threadIdx.x;
    if (i < N) {
        int o = offs[i] + bsum[i / SCAN_BLK];
        offs[i] = o;
        cursor[i] = o;
    }
    if (i == 0) offs[N] = E;
}

__global__ void k_fill(const int* __restrict__ src, const int* __restrict__ dst,
                       int* __restrict__ cursor, int* __restrict__ csr, int E) {
    int e = blockIdx.x * blockDim.x + threadIdx.x;
    if (e >= E) return;
    unsigned s = (unsigned)src[e];
    unsigned d = (unsigned)dst[e];
    if (s >= NN || d >= NN) return;
    int pos = atomicAdd(cursor + d, 1);
    csr[pos] = (int)s;
}

// ---------------- dual GEMM: z = x @ [Wl | Wr]  via FFMA2 ----------------
// block = 256 threads; tile = 64 nodes x 128 cols; thread tile = 4 nodes x 8 cols
template <int DIN>
__global__ void k_gemm_dual(const float* __restrict__ x,
                            const float* __restrict__ Wl,
                            const float* __restrict__ Wr,
                            float* __restrict__ zl,
                            float* __restrict__ zr, int N) {
    extern __shared__ float sm[];
    float* ws = sm;                 // DIN * 128 (cols: [Wl | Wr])
    float* xs = sm + DIN * 128;     // 64 * DIN (node-major)
    const int tid = threadIdx.x;

    for (int i = tid; i < DIN * 128; i += 256) {
        int k = i >> 7, j = i & 127;
        ws[i] = (j < 64) ? Wl[k * 64 + j] : Wr[k * 64 + (j - 64)];
    }
    const int base = blockIdx.x * 64;
    constexpr int KQ = DIN / 4;
    for (int i = tid; i < 64 * KQ; i += 256) {
        int n = i / KQ, kq = i % KQ;
        int node = base + n;
        float4 v = (node < N) ? *(const float4*)(x + (size_t)node * DIN + kq * 4)
                              : make_float4(0.f, 0.f, 0.f, 0.f);
        *(float4*)(xs + n * DIN + kq * 4) = v;
    }
    __syncthreads();

    const int tx = tid & 15;   // cols [8*tx, 8*tx+8)
    const int ty = tid >> 4;   // nodes [base+4*ty, base+4*ty+4)

    unsigned long long acc[4][4];   // [node][col-pair], each = 2 fp32
#pragma unroll
    for (int a = 0; a < 4; a++)
#pragma unroll
        for (int p = 0; p < 4; p++) acc[a][p] = 0ull;

    const float* xs0 = xs + (ty * 4) * DIN;
    const float* wc = ws + tx * 8;
#pragma unroll 4
    for (int k = 0; k < DIN; k++) {
        // 8 weight cols as 4 packed pairs (two LDS.128)
        ulonglong2 wa = *(const ulonglong2*)(wc + k * 128);
        ulonglong2 wb = *(const ulonglong2*)(wc + k * 128 + 4);
        unsigned long long xp[4];
#pragma unroll
        for (int a = 0; a < 4; a++) xp[a] = pack2(xs0[a * DIN + k]);
#pragma unroll
        for (int a = 0; a < 4; a++) {
            ffma2(acc[a][0], xp[a], wa.x);
            ffma2(acc[a][1], xp[a], wa.y);
            ffma2(acc[a][2], xp[a], wb.x);
            ffma2(acc[a][3], xp[a], wb.y);
        }
    }

    const int col = tx * 8;
#pragma unroll
    for (int a = 0; a < 4; a++) {
        int node = base + ty * 4 + a;
        if (node >= N) continue;
        float2 p0 = *(float2*)&acc[a][0];
        float2 p1 = *(float2*)&acc[a][1];
        float2 p2 = *(float2*)&acc[a][2];
        float2 p3 = *(float2*)&acc[a][3];
        float4 v0 = make_float4(p0.x, p0.y, p1.x, p1.y);
        float4 v1 = make_float4(p2.x, p2.y, p3.x, p3.y);
        if (col < 64) {
            float* o = zl + (size_t)node * 64 + col;
            *(float4*)o = v0;
            *(float4*)(o + 4) = v1;
        } else {
            float* o = zr + (size_t)node * 64 + (col - 64);
            *(float4*)o = v0;
            *(float4*)(o + 4) = v1;
        }
    }
}

// ---------------- CSR gather + combine (unroll-2 for MLP) ----------------
__global__ void k_gather(const int* __restrict__ offs, const int* __restrict__ csr,
                         const float* __restrict__ zl, const float* __restrict__ zr,
                         const float* __restrict__ bl, float* __restrict__ h, int N) {
    int tid = threadIdx.x;
    int node = blockIdx.x * 16 + (tid >> 4);
    int c = (tid & 15) * 4;
    if (node >= N) return;
    int s0 = offs[node], s1 = offs[node + 1];
    float4 acc = make_float4(0.f, 0.f, 0.f, 0.f);
    int i = s0;
    for (; i + 2 <= s1; i += 2) {
        int sa = __ldg(csr + i);
        int sb = __ldg(csr + i + 1);
        float4 va = *(const float4*)(zl + (size_t)sa * 64 + c);
        float4 vb = *(const float4*)(zl + (size_t)sb * 64 + c);
        acc.x += va.x + vb.x;
        acc.y += va.y + vb.y;
        acc.z += va.z + vb.z;
        acc.w += va.w + vb.w;
    }
    if (i < s1) {
        int sa = __ldg(csr + i);
        float4 va = *(const float4*)(zl + (size_t)sa * 64 + c);
        acc.x += va.x; acc.y += va.y; acc.z += va.z; acc.w += va.w;
    }
    float iv = 1.0f / fmaxf((float)(s1 - s0), 1.0f);
    float4 r = *(const float4*)(zr + (size_t)node * 64 + c);
    float4 b = *(const float4*)(bl + c);
    float4 o;
    o.x = acc.x * iv + r.x + b.x;
    o.y = acc.y * iv + r.y + b.y;
    o.z = acc.z * iv + r.z + b.z;
    o.w = acc.w * iv + r.w + b.w;
    *(float4*)(h + (size_t)node * 64 + c) = o;
}

// layer-3 variant: fuse global mean-pool accumulation, skip writing h
__global__ void k_gather_pool(const int* __restrict__ offs, const int* __restrict__ csr,
                              const float* __restrict__ zl, const float* __restrict__ zr,
                              const float* __restrict__ bl, const int* __restrict__ batch,
                              float* __restrict__ pool, float* __restrict__ pcnt, int N) {
    int tid = threadIdx.x;
    int node = blockIdx.x * 16 + (tid >> 4);
    int c = (tid & 15) * 4;
    if (node >= N) return;
    int s0 = offs[node], s1 = offs[node + 1];
    float4 acc = make_float4(0.f, 0.f, 0.f, 0.f);
    int i = s0;
    for (; i + 2 <= s1; i += 2) {
        int sa = __ldg(csr + i);
        int sb = __ldg(csr + i + 1);
        float4 va = *(const float4*)(zl + (size_t)sa * 64 + c);
        float4 vb = *(const float4*)(zl + (size_t)sb * 64 + c);
        acc.x += va.x + vb.x;
        acc.y += va.y + vb.y;
        acc.z += va.z + vb.z;
        acc.w += va.w + vb.w;
    }
    if (i < s1) {
        int sa = __ldg(csr + i);
        float4 va = *(const float4*)(zl + (size_t)sa * 64 + c);
        acc.x += va.x; acc.y += va.y; acc.z += va.z; acc.w += va.w;
    }
    float iv = 1.0f / fmaxf((float)(s1 - s0), 1.0f);
    float4 r = *(const float4*)(zr + (size_t)node * 64 + c);
    float4 b = *(const float4*)(bl + c);
    float4 o;
    o.x = acc.x * iv + r.x + b.x;
    o.y = acc.y * iv + r.y + b.y;
    o.z = acc.z * iv + r.z + b.z;
    o.w = acc.w * iv + r.w + b.w;
    unsigned g = (unsigned)batch[node];
    if (g < GG) {
        red_add_v4(pool + (size_t)g * 64 + c, o);
        if (c == 0) red_add_f(pcnt + g, 1.0f);
    }
}

__global__ void k_poolfin(const float* __restrict__ pool, const float* __restrict__ pcnt,
                          float* __restrict__ c0) {
    int idx = blockIdx.x * blockDim.x + threadIdx.x;
    if (idx >= GG * 64) return;
    int g = idx >> 6;
    c0[idx] = pool[idx] / fmaxf(pcnt[g], 1.0f);
}

// ---------------- fused Linear + BatchNorm(batch stats) + tanh ----------------
__global__ void k_lin_bn_tanh(const float* __restrict__ in, int din,
                              const float* __restrict__ W, const float* __restrict__ b,
                              const float* __restrict__ gamma, const float* __restrict__ beta,
                              float* __restrict__ out, int dout) {
    __shared__ float ws[256];
    __shared__ float red[256];
    const int col = blockIdx.x;
    const int tid = threadIdx.x;
    if (tid < din) ws[tid] = W[tid * dout + col];
    __syncthreads();

    float val = b[col];
    const float* row = in + tid * din;
    for (int k = 0; k < din; k++) val += row[k] * ws[k];

    red[tid] = val;
    __syncthreads();
    for (int s = 128; s > 0; s >>= 1) {
        if (tid < s) red[tid] += red[tid + s];
        __syncthreads();
    }
    float mean = red[0] * (1.0f / 256.0f);
    __syncthreads();

    float dv = val - mean;
    red[tid] = dv * dv;
    __syncthreads();
    for (int s = 128; s > 0; s >>= 1) {
        if (tid < s) red[tid] += red[tid + s];
        __syncthreads();
    }
    float var = red[0] * (1.0f / 256.0f);

    float y = dv * rsqrtf(var + 1e-5f) * gamma[col] + beta[col];
    out[tid * dout + col] = tanhf(y);
}

// ---------------- final linear 64 -> 10 ----------------
__global__ void k_final(const float* __restrict__ in, const float* __restrict__ W,
                        const float* __restrict__ b, float* __restrict__ out) {
    __shared__ float ws[64 * 10];
    __shared__ float bs[10];
    const int tid = threadIdx.x;
    for (int i = tid; i < 640; i += 256) ws[i] = W[i];
    if (tid < 10) bs[tid] = b[tid];
    __syncthreads();
    float acc[10];
#pragma unroll
    for (int j = 0; j < 10; j++) acc[j] = bs[j];
    const float* row = in + tid * 64;
    for (int k = 0; k < 64; k++) {
        float xv = row[k];
#pragma unroll
        for (int j = 0; j < 10; j++) acc[j] += xv * ws[k * 10 + j];
    }
#pragma unroll
    for (int j = 0; j < 10; j++) out[tid * 10 + j] = acc[j];
}

// ---------------- launch ----------------
extern "C" void kernel_launch(void* const* d_in, const int* in_sizes, int n_in,
                              void* d_out, int out_size) {
    const float* x = (const float*)d_in[0];
    const int* ei = (const int*)d_in[1];
    const int* batch = (const int*)d_in[2];
    const float* W1l = (const float*)d_in[3];
    const float* b1l = (const float*)d_in[4];
    const float* W1r = (const float*)d_in[5];
    const float* W2l = (const float*)d_in[6];
    const float* b2l = (const float*)d_in[7];
    const float* W2r = (const float*)d_in[8];
    const float* W3l = (const float*)d_in[9];
    const float* b3l = (const float*)d_in[10];
    const float* W3r = (const float*)d_in[11];
    const float* lin1_w = (const float*)d_in[12];
    const float* lin1_b = (const float*)d_in[13];
    const float* g1 = (const float*)d_in[14];
    const float* be1 = (const float*)d_in[15];
    const float* lin2_w = (const float*)d_in[16];
    const float* lin2_b = (const float*)d_in[17];
    const float* g2 = (const float*)d_in[18];
    const float* be2 = (const float*)d_in[19];
    const float* lin3_w = (const float*)d_in[20];
    const float* lin3_b = (const float*)d_in[21];
    const float* g3 = (const float*)d_in[22];
    const float* be3 = (const float*)d_in[23];
    const float* lin4_w = (const float*)d_in[24];
    const float* lin4_b = (const float*)d_in[25];

    const int N = in_sizes[0] / INW;   // 50000
    const int E = in_sizes[1] / 2;     // 800000
    const int* src = ei;
    const int* dst = ei + E;

    float *zl, *zr, *h, *pool, *pcnt, *cA, *cB;
    int *cnt, *offs, *cursor, *csr, *bsum;
    cudaGetSymbolAddress((void**)&zl, g_zl);
    cudaGetSymbolAddress((void**)&zr, g_zr);
    cudaGetSymbolAddress((void**)&h, g_h);
    cudaGetSymbolAddress((void**)&cnt, g_cnt);
    cudaGetSymbolAddress((void**)&offs, g_offs);
    cudaGetSymbolAddress((void**)&cursor, g_cursor);
    cudaGetSymbolAddress((void**)&csr, g_csr);
    cudaGetSymbolAddress((void**)&bsum, g_bsum);
    cudaGetSymbolAddress((void**)&pool, g_pool);
    cudaGetSymbolAddress((void**)&pcnt, g_pcnt);
    cudaGetSymbolAddress((void**)&cA, g_cA);
    cudaGetSymbolAddress((void**)&cB, g_cB);

    const int SMEM1 = (INW * 128 + 64 * INW) * 4;   // 98304
    const int SMEM2 = (64 * 128 + 64 * 64) * 4;     // 49152
    cudaFuncSetAttribute(k_gemm_dual<128>, cudaFuncAttributeMaxDynamicSharedMemorySize, SMEM1);
    cudaFuncSetAttribute(k_gemm_dual<64>, cudaFuncAttributeMaxDynamicSharedMemorySize, SMEM2);

    const int gemm_blocks = (N + 63) / 64;
    const int gat_blocks = (N + 15) / 16;

    // ---- CSR build (once, reused by all 3 layers) ----
    cudaMemsetAsync(cnt, 0, (size_t)N * sizeof(int), 0);
    k_count<<<(E + 255) / 256, 256>>>(dst, cnt, E);
    k_scan1<<<NBLK, SCAN_BLK>>>(cnt, offs, bsum, N);
    k_scan2<<<1, 128>>>(bsum, NBLK);
    k_scan3<<<(N + 255) / 256, 256>>>(offs, bsum, cursor, N, E);
    k_fill<<<(E + 255) / 256, 256>>>(src, dst, cursor, csr, E);

    // ---- layer 1 ----
    k_gemm_dual<128><<<gemm_blocks, 256, SMEM1>>>(x, W1l, W1r, zl, zr, N);
    k_gather<<<gat_blocks, 256>>>(offs, csr, zl, zr, b1l, h, N);

    // ---- layer 2 ----
    k_gemm_dual<64><<<gemm_blocks, 256, SMEM2>>>(h, W2l, W2r, zl, zr, N);
    k_gather<<<gat_blocks, 256>>>(offs, csr, zl, zr, b2l, h, N);

    // ---- layer 3 + fused global mean pool ----
    k_gemm_dual<64><<<gemm_blocks, 256, SMEM2>>>(h, W3l, W3r, zl, zr, N);
    cudaMemsetAsync(pool, 0, (size_t)GG * 64 * sizeof(float), 0);
    cudaMemsetAsync(pcnt, 0, (size_t)GG * sizeof(float), 0);
    k_gather_pool<<<gat_blocks, 256>>>(offs, csr, zl, zr, b3l, batch, pool, pcnt, N);
    k_poolfin<<<(GG * 64 + 255) / 256, 256>>>(pool, pcnt, cA);

    // ---- MLP head ----
    k_lin_bn_tanh<<<256, 256>>>(cA, 64, lin1_w, lin1_b, g1, be1, cB, 256);
    k_lin_bn_tanh<<<128, 256>>>(cB, 256, lin2_w, lin2_b, g2, be2, cA, 128);
    k_lin_bn_tanh<<<64, 256>>>(cA, 128, lin3_w, lin3_b, g3, be3, cB, 64);
    k_final<<<1, 256>>>(cB, lin4_w, lin4_b, (float*)d_out);
}

// round 9
// speedup vs baseline: 1.4833x; 1.4833x over previous
#include <cuda_runtime.h>
#include <cstdint>

// ---------------- problem constants ----------------
#define NN 50000
#define EE 800000
#define GG 256
#define HH 64
#define INW 128
#define SCAN_BLK 512
#define NBLK ((NN + SCAN_BLK - 1) / SCAN_BLK)   // 98

// ---------------- device scratch (no allocation allowed) ----------------
__device__ float g_zl[NN * HH];
__device__ float g_zr[NN * HH];
__device__ float g_h[NN * HH];
__device__ int   g_cnt[NN];
__device__ int   g_offs[NN + 1];
__device__ int   g_cursor[NN];
__device__ int   g_csr[EE];
__device__ int   g_bsum[128];
__device__ float g_pool[GG * HH];
__device__ float g_pcnt[GG];
__device__ float g_cA[GG * 256];
__device__ float g_cB[GG * 256];

// ---------------- helpers ----------------
__device__ __forceinline__ void red_add_v4(float* a, float4 v) {
    asm volatile("red.global.add.v4.f32 [%0], {%1,%2,%3,%4};"
                 :: "l"(a), "f"(v.x), "f"(v.y), "f"(v.z), "f"(v.w) : "memory");
}
__device__ __forceinline__ void red_add_f(float* a, float v) {
    asm volatile("red.global.add.f32 [%0], %1;" :: "l"(a), "f"(v) : "memory");
}

// ---------------- CSR build ----------------
__global__ void k_count(const int* __restrict__ dst, int* __restrict__ cnt, int E) {
    int e = blockIdx.x * blockDim.x + threadIdx.x;
    if (e >= E) return;
    unsigned d = (unsigned)dst[e];
    if (d < NN) atomicAdd(cnt + d, 1);
}

__global__ void k_scan1(const int* __restrict__ cnt, int* __restrict__ offs,
                        int* __restrict__ bsum, int N) {
    __shared__ int sh[SCAN_BLK];
    int i = blockIdx.x * SCAN_BLK + threadIdx.x;
    int v = (i < N) ? cnt[i] : 0;
    sh[threadIdx.x] = v;
    __syncthreads();
    for (int d = 1; d < SCAN_BLK; d <<= 1) {
        int t = (threadIdx.x >= d) ? sh[threadIdx.x - d] : 0;
        __syncthreads();
        sh[threadIdx.x] += t;
        __syncthreads();
    }
    if (i < N) offs[i] = sh[threadIdx.x] - v;   // exclusive
    if (threadIdx.x == SCAN_BLK - 1) bsum[blockIdx.x] = sh[SCAN_BLK - 1];
}

__global__ void k_scan2(int* __restrict__ bsum, int nb) {
    __shared__ int sh[128];
    int v = (threadIdx.x < nb) ? bsum[threadIdx.x] : 0;
    sh[threadIdx.x] = v;
    __syncthreads();
    for (int d = 1; d < 128; d <<= 1) {
        int t = (threadIdx.x >= d) ? sh[threadIdx.x - d] : 0;
        __syncthreads();
        sh[threadIdx.x] += t;
        __syncthreads();
    }
    if (threadIdx.x < nb) bsum[threadIdx.x] = sh[threadIdx.x] - v;   // exclusive
}

__global__ void k_scan3(int* __restrict__ offs, const int* __restrict__ bsum,
                        int* __restrict__ cursor, int N, int E) {
    int i = blockIdx.x * blockDim.x + threadIdx.x;
    if (i < N) {
        int o = offs[i] + bsum[i / SCAN_BLK];
        offs[i] = o;
        cursor[i] = o;
    }
    if (i == 0) offs[N] = E;
}

__global__ void k_fill(const int* __restrict__ src, const int* __restrict__ dst,
                       int* __restrict__ cursor, int* __restrict__ csr, int E) {
    int e = blockIdx.x * blockDim.x + threadIdx.x;
    if (e >= E) return;
    unsigned s = (unsigned)src[e];
    unsigned d = (unsigned)dst[e];
    if (s >= NN || d >= NN) return;
    int pos = atomicAdd(cursor + d, 1);
    csr[pos] = (int)s;
}

// ---------------- dual GEMM: z = x @ [Wl | Wr]  (DIN x 64 each) ----------------
// block = 256 threads, tile = 32 nodes x 128 cols, thread tile = 4 nodes x 4 cols
template <int DIN>
__global__ void k_gemm_dual(const float* __restrict__ x,
                            const float* __restrict__ Wl,
                            const float* __restrict__ Wr,
                            float* __restrict__ zl,
                            float* __restrict__ zr, int N) {
    extern __shared__ float sm[];
    float* ws = sm;                 // DIN * 128
    float* xs = sm + DIN * 128;     // 32 * DIN
    const int tid = threadIdx.x;

    for (int i = tid; i < DIN * 128; i += 256) {
        int k = i >> 7, j = i & 127;
        ws[i] = (j < 64) ? Wl[k * 64 + j] : Wr[k * 64 + (j - 64)];
    }
    const int base = blockIdx.x * 32;
    for (int i = tid; i < 32 * DIN; i += 256) {
        int n = i / DIN, k = i % DIN;
        int node = base + n;
        xs[i] = (node < N) ? x[(long long)node * DIN + k] : 0.0f;
    }
    __syncthreads();

    const int tx = tid & 31;
    const int ty = tid >> 5;
    float acc[4][4];
#pragma unroll
    for (int a = 0; a < 4; a++)
#pragma unroll
        for (int b = 0; b < 4; b++) acc[a][b] = 0.0f;

    const float* xs0 = xs + (ty * 4) * DIN;
#pragma unroll 4
    for (int k = 0; k < DIN; k++) {
        float4 w = *(const float4*)(ws + k * 128 + tx * 4);
        float xv[4];
#pragma unroll
        for (int a = 0; a < 4; a++) xv[a] = xs0[a * DIN + k];
#pragma unroll
        for (int a = 0; a < 4; a++) {
            acc[a][0] += xv[a] * w.x;
            acc[a][1] += xv[a] * w.y;
            acc[a][2] += xv[a] * w.z;
            acc[a][3] += xv[a] * w.w;
        }
    }

    const int col = tx * 4;
#pragma unroll
    for (int a = 0; a < 4; a++) {
        int node = base + ty * 4 + a;
        if (node < N) {
            float4 v = make_float4(acc[a][0], acc[a][1], acc[a][2], acc[a][3]);
            if (col < 64)
                *(float4*)(zl + (long long)node * 64 + col) = v;
            else
                *(float4*)(zr + (long long)node * 64 + (col - 64)) = v;
        }
    }
}

// ---------------- CSR gather + combine (shuffle-cooperative) ----------------
// 16 lanes per node. Per 16-edge chunk: each lane loads ONE csr index
// (coalesced), then 16 shfl broadcasts give 16 independent float4 gathers
// in flight per lane.
__global__ void k_gather(const int* __restrict__ offs, const int* __restrict__ csr,
                         const float* __restrict__ zl, const float* __restrict__ zr,
                         const float* __restrict__ bl, float* __restrict__ h, int N) {
    const int tid = threadIdx.x;
    const int node = blockIdx.x * 16 + (tid >> 4);
    const int lane = tid & 15;
    const int c = lane * 4;
    if (node >= N) return;
    const unsigned segmask = 0xFFFFu << (threadIdx.x & 16);
    int s0 = offs[node], s1 = offs[node + 1];
    float4 acc = make_float4(0.f, 0.f, 0.f, 0.f);

    int e = s0;
    for (; e + 16 <= s1; e += 16) {
        int idx = __ldg(csr + e + lane);
#pragma unroll
        for (int j = 0; j < 16; j++) {
            int s = __shfl_sync(segmask, idx, j, 16);
            float4 v = *(const float4*)(zl + (size_t)s * 64 + c);
            acc.x += v.x; acc.y += v.y; acc.z += v.z; acc.w += v.w;
        }
    }
    if (e < s1) {
        int my = e + lane;
        int idx = (my < s1) ? __ldg(csr + my) : 0;
        int m = s1 - e;
        for (int j = 0; j < m; j++) {
            int s = __shfl_sync(segmask, idx, j, 16);
            float4 v = *(const float4*)(zl + (size_t)s * 64 + c);
            acc.x += v.x; acc.y += v.y; acc.z += v.z; acc.w += v.w;
        }
    }

    float iv = 1.0f / fmaxf((float)(s1 - s0), 1.0f);
    float4 r = *(const float4*)(zr + (size_t)node * 64 + c);
    float4 b = *(const float4*)(bl + c);
    float4 o;
    o.x = acc.x * iv + r.x + b.x;
    o.y = acc.y * iv + r.y + b.y;
    o.z = acc.z * iv + r.z + b.z;
    o.w = acc.w * iv + r.w + b.w;
    *(float4*)(h + (size_t)node * 64 + c) = o;
}

// layer-3 variant: fuse global mean-pool accumulation, skip writing h
__global__ void k_gather_pool(const int* __restrict__ offs, const int* __restrict__ csr,
                              const float* __restrict__ zl, const float* __restrict__ zr,
                              const float* __restrict__ bl, const int* __restrict__ batch,
                              float* __restrict__ pool, float* __restrict__ pcnt, int N) {
    const int tid = threadIdx.x;
    const int node = blockIdx.x * 16 + (tid >> 4);
    const int lane = tid & 15;
    const int c = lane * 4;
    if (node >= N) return;
    const unsigned segmask = 0xFFFFu << (threadIdx.x & 16);
    int s0 = offs[node], s1 = offs[node + 1];
    float4 acc = make_float4(0.f, 0.f, 0.f, 0.f);

    int e = s0;
    for (; e + 16 <= s1; e += 16) {
        int idx = __ldg(csr + e + lane);
#pragma unroll
        for (int j = 0; j < 16; j++) {
            int s = __shfl_sync(segmask, idx, j, 16);
            float4 v = *(const float4*)(zl + (size_t)s * 64 + c);
            acc.x += v.x; acc.y += v.y; acc.z += v.z; acc.w += v.w;
        }
    }
    if (e < s1) {
        int my = e + lane;
        int idx = (my < s1) ? __ldg(csr + my) : 0;
        int m = s1 - e;
        for (int j = 0; j < m; j++) {
            int s = __shfl_sync(segmask, idx, j, 16);
            float4 v = *(const float4*)(zl + (size_t)s * 64 + c);
            acc.x += v.x; acc.y += v.y; acc.z += v.z; acc.w += v.w;
        }
    }

    float iv = 1.0f / fmaxf((float)(s1 - s0), 1.0f);
    float4 r = *(const float4*)(zr + (size_t)node * 64 + c);
    float4 b = *(const float4*)(bl + c);
    float4 o;
    o.x = acc.x * iv + r.x + b.x;
    o.y = acc.y * iv + r.y + b.y;
    o.z = acc.z * iv + r.z + b.z;
    o.w = acc.w * iv + r.w + b.w;
    unsigned g = (unsigned)batch[node];
    if (g < GG) {
        red_add_v4(pool + (size_t)g * 64 + c, o);
        if (c == 0) red_add_f(pcnt + g, 1.0f);
    }
}

__global__ void k_poolfin(const float* __restrict__ pool, const float* __restrict__ pcnt,
                          float* __restrict__ c0) {
    int idx = blockIdx.x * blockDim.x + threadIdx.x;
    if (idx >= GG * 64) return;
    int g = idx >> 6;
    c0[idx] = pool[idx] / fmaxf(pcnt[g], 1.0f);
}

// ---------------- fused Linear + BatchNorm(batch stats) + tanh ----------------
__global__ void k_lin_bn_tanh(const float* __restrict__ in, int din,
                              const float* __restrict__ W, const float* __restrict__ b,
                              const float* __restrict__ gamma, const float* __restrict__ beta,
                              float* __restrict__ out, int dout) {
    __shared__ float ws[256];
    __shared__ float red[256];
    const int col = blockIdx.x;
    const int tid = threadIdx.x;
    if (tid < din) ws[tid] = W[tid * dout + col];
    __syncthreads();

    float val = b[col];
    const float* row = in + tid * din;
    for (int k = 0; k < din; k++) val += row[k] * ws[k];

    red[tid] = val;
    __syncthreads();
    for (int s = 128; s > 0; s >>= 1) {
        if (tid < s) red[tid] += red[tid + s];
        __syncthreads();
    }
    float mean = red[0] * (1.0f / 256.0f);
    __syncthreads();

    float dv = val - mean;
    red[tid] = dv * dv;
    __syncthreads();
    for (int s = 128; s > 0; s >>= 1) {
        if (tid < s) red[tid] += red[tid + s];
        __syncthreads();
    }
    float var = red[0] * (1.0f / 256.0f);

    float y = dv * rsqrtf(var + 1e-5f) * gamma[col] + beta[col];
    out[tid * dout + col] = tanhf(y);
}

// ---------------- final linear 64 -> 10 ----------------
__global__ void k_final(const float* __restrict__ in, const float* __restrict__ W,
                        const float* __restrict__ b, float* __restrict__ out) {
    __shared__ float ws[64 * 10];
    __shared__ float bs[10];
    const int tid = threadIdx.x;
    for (int i = tid; i < 640; i += 256) ws[i] = W[i];
    if (tid < 10) bs[tid] = b[tid];
    __syncthreads();
    float acc[10];
#pragma unroll
    for (int j = 0; j < 10; j++) acc[j] = bs[j];
    const float* row = in + tid * 64;
    for (int k = 0; k < 64; k++) {
        float xv = row[k];
#pragma unroll
        for (int j = 0; j < 10; j++) acc[j] += xv * ws[k * 10 + j];
    }
#pragma unroll
    for (int j = 0; j < 10; j++) out[tid * 10 + j] = acc[j];
}

// ---------------- launch ----------------
extern "C" void kernel_launch(void* const* d_in, const int* in_sizes, int n_in,
                              void* d_out, int out_size) {
    const float* x = (const float*)d_in[0];
    const int* ei = (const int*)d_in[1];
    const int* batch = (const int*)d_in[2];
    const float* W1l = (const float*)d_in[3];
    const float* b1l = (const float*)d_in[4];
    const float* W1r = (const float*)d_in[5];
    const float* W2l = (const float*)d_in[6];
    const float* b2l = (const float*)d_in[7];
    const float* W2r = (const float*)d_in[8];
    const float* W3l = (const float*)d_in[9];
    const float* b3l = (const float*)d_in[10];
    const float* W3r = (const float*)d_in[11];
    const float* lin1_w = (const float*)d_in[12];
    const float* lin1_b = (const float*)d_in[13];
    const float* g1 = (const float*)d_in[14];
    const float* be1 = (const float*)d_in[15];
    const float* lin2_w = (const float*)d_in[16];
    const float* lin2_b = (const float*)d_in[17];
    const float* g2 = (const float*)d_in[18];
    const float* be2 = (const float*)d_in[19];
    const float* lin3_w = (const float*)d_in[20];
    const float* lin3_b = (const float*)d_in[21];
    const float* g3 = (const float*)d_in[22];
    const float* be3 = (const float*)d_in[23];
    const float* lin4_w = (const float*)d_in[24];
    const float* lin4_b = (const float*)d_in[25];

    const int N = in_sizes[0] / INW;   // 50000
    const int E = in_sizes[1] / 2;     // 800000
    const int* src = ei;
    const int* dst = ei + E;

    float *zl, *zr, *h, *pool, *pcnt, *cA, *cB;
    int *cnt, *offs, *cursor, *csr, *bsum;
    cudaGetSymbolAddress((void**)&zl, g_zl);
    cudaGetSymbolAddress((void**)&zr, g_zr);
    cudaGetSymbolAddress((void**)&h, g_h);
    cudaGetSymbolAddress((void**)&cnt, g_cnt);
    cudaGetSymbolAddress((void**)&offs, g_offs);
    cudaGetSymbolAddress((void**)&cursor, g_cursor);
    cudaGetSymbolAddress((void**)&csr, g_csr);
    cudaGetSymbolAddress((void**)&bsum, g_bsum);
    cudaGetSymbolAddress((void**)&pool, g_pool);
    cudaGetSymbolAddress((void**)&pcnt, g_pcnt);
    cudaGetSymbolAddress((void**)&cA, g_cA);
    cudaGetSymbolAddress((void**)&cB, g_cB);

    const int SMEM1 = (INW * 128 + 32 * INW) * 4;   // 81920
    const int SMEM2 = (64 * 128 + 32 * 64) * 4;     // 40960
    cudaFuncSetAttribute(k_gemm_dual<128>, cudaFuncAttributeMaxDynamicSharedMemorySize, SMEM1);
    cudaFuncSetAttribute(k_gemm_dual<64>, cudaFuncAttributeMaxDynamicSharedMemorySize, SMEM2);

    const int gemm_blocks = (N + 31) / 32;
    const int gat_blocks = (N + 15) / 16;

    // ---- CSR build (once, reused by all 3 layers) ----
    cudaMemsetAsync(cnt, 0, (size_t)N * sizeof(int), 0);
    k_count<<<(E + 255) / 256, 256>>>(dst, cnt, E);
    k_scan1<<<NBLK, SCAN_BLK>>>(cnt, offs, bsum, N);
    k_scan2<<<1, 128>>>(bsum, NBLK);
    k_scan3<<<(N + 255) / 256, 256>>>(offs, bsum, cursor, N, E);
    k_fill<<<(E + 255) / 256, 256>>>(src, dst, cursor, csr, E);

    // ---- layer 1 ----
    k_gemm_dual<128><<<gemm_blocks, 256, SMEM1>>>(x, W1l, W1r, zl, zr, N);
    k_gather<<<gat_blocks, 256>>>(offs, csr, zl, zr, b1l, h, N);

    // ---- layer 2 ----
    k_gemm_dual<64><<<gemm_blocks, 256, SMEM2>>>(h, W2l, W2r, zl, zr, N);
    k_gather<<<gat_blocks, 256>>>(offs, csr, zl, zr, b2l, h, N);

    // ---- layer 3 + fused global mean pool ----
    k_gemm_dual<64><<<gemm_blocks, 256, SMEM2>>>(h, W3l, W3r, zl, zr, N);
    cudaMemsetAsync(pool, 0, (size_t)GG * 64 * sizeof(float), 0);
    cudaMemsetAsync(pcnt, 0, (size_t)GG * sizeof(float), 0);
    k_gather_pool<<<gat_blocks, 256>>>(offs, csr, zl, zr, b3l, batch, pool, pcnt, N);
    k_poolfin<<<(GG * 64 + 255) / 256, 256>>>(pool, pcnt, cA);

    // ---- MLP head ----
    k_lin_bn_tanh<<<256, 256>>>(cA, 64, lin1_w, lin1_b, g1, be1, cB, 256);
    k_lin_bn_tanh<<<128, 256>>>(cB, 256, lin2_w, lin2_b, g2, be2, cA, 128);
    k_lin_bn_tanh<<<64, 256>>>(cA, 128, lin3_w, lin3_b, g3, be3, cB, 64);
    k_final<<<1, 256>>>(cB, lin4_w, lin4_b, (float*)d_out);
}

// round 10
// speedup vs baseline: 1.5680x; 1.0571x over previous
#include <cuda_runtime.h>
#include <cuda_bf16.h>
#include <cstdint>

// ---------------- problem constants ----------------
#define NN 50000
#define EE 800000
#define GG 256
#define HH 64
#define INW 128
#define SCAN_BLK 512
#define NBLK ((NN + SCAN_BLK - 1) / SCAN_BLK)   // 98

// ---------------- device scratch (no allocation allowed) ----------------
__device__ __nv_bfloat16 g_zlb[NN * HH];   // messages in bf16 (gather traffic halved)
__device__ float g_zr[NN * HH];
__device__ float g_h[NN * HH];
__device__ int   g_cnt[NN];
__device__ int   g_offs[NN + 1];
__device__ int   g_cursor[NN];
__device__ int   g_csr[EE];
__device__ int   g_bsum[128];
__device__ float g_pool[GG * HH];
__device__ float g_pcnt[GG];
__device__ float g_cA[GG * 256];
__device__ float g_cB[GG * 256];

// ---------------- helpers ----------------
__device__ __forceinline__ void red_add_v4(float* a, float4 v) {
    asm volatile("red.global.add.v4.f32 [%0], {%1,%2,%3,%4};"
                 :: "l"(a), "f"(v.x), "f"(v.y), "f"(v.z), "f"(v.w) : "memory");
}
__device__ __forceinline__ void red_add_f(float* a, float v) {
    asm volatile("red.global.add.f32 [%0], %1;" :: "l"(a), "f"(v) : "memory");
}
__device__ __forceinline__ float4 bf4_to_f4(uint2 u) {
    __nv_bfloat162 p0 = *(__nv_bfloat162*)&u.x;
    __nv_bfloat162 p1 = *(__nv_bfloat162*)&u.y;
    float2 a = __bfloat1622float2(p0);
    float2 b = __bfloat1622float2(p1);
    return make_float4(a.x, a.y, b.x, b.y);
}

// ---------------- CSR build ----------------
__global__ void k_count(const int* __restrict__ dst, int* __restrict__ cnt, int E) {
    int e = blockIdx.x * blockDim.x + threadIdx.x;
    if (e >= E) return;
    unsigned d = (unsigned)dst[e];
    if (d < NN) atomicAdd(cnt + d, 1);
}

__global__ void k_scan1(const int* __restrict__ cnt, int* __restrict__ offs,
                        int* __restrict__ bsum, int N) {
    __shared__ int sh[SCAN_BLK];
    int i = blockIdx.x * SCAN_BLK + threadIdx.x;
    int v = (i < N) ? cnt[i] : 0;
    sh[threadIdx.x] = v;
    __syncthreads();
    for (int d = 1; d < SCAN_BLK; d <<= 1) {
        int t = (threadIdx.x >= d) ? sh[threadIdx.x - d] : 0;
        __syncthreads();
        sh[threadIdx.x] += t;
        __syncthreads();
    }
    if (i < N) offs[i] = sh[threadIdx.x] - v;   // exclusive
    if (threadIdx.x == SCAN_BLK - 1) bsum[blockIdx.x] = sh[SCAN_BLK - 1];
}

__global__ void k_scan2(int* __restrict__ bsum, int nb) {
    __shared__ int sh[128];
    int v = (threadIdx.x < nb) ? bsum[threadIdx.x] : 0;
    sh[threadIdx.x] = v;
    __syncthreads();
    for (int d = 1; d < 128; d <<= 1) {
        int t = (threadIdx.x >= d) ? sh[threadIdx.x - d] : 0;
        __syncthreads();
        sh[threadIdx.x] += t;
        __syncthreads();
    }
    if (threadIdx.x < nb) bsum[threadIdx.x] = sh[threadIdx.x] - v;   // exclusive
}

__global__ void k_scan3(int* __restrict__ offs, const int* __restrict__ bsum,
                        int* __restrict__ cursor, int N, int E) {
    int i = blockIdx.x * blockDim.x + threadIdx.x;
    if (i < N) {
        int o = offs[i] + bsum[i / SCAN_BLK];
        offs[i] = o;
        cursor[i] = o;
    }
    if (i == 0) offs[N] = E;
}

__global__ void k_fill(const int* __restrict__ src, const int* __restrict__ dst,
                       int* __restrict__ cursor, int* __restrict__ csr, int E) {
    int e = blockIdx.x * blockDim.x + threadIdx.x;
    if (e >= E) return;
    unsigned s = (unsigned)src[e];
    unsigned d = (unsigned)dst[e];
    if (s >= NN || d >= NN) return;
    int pos = atomicAdd(cursor + d, 1);
    csr[pos] = (int)s;
}

// ---------------- dual GEMM: zl(bf16) = x @ Wl, zr(f32) = x @ Wr ----------------
// block = 256 threads, tile = 32 nodes x 128 cols, thread tile = 4 nodes x 4 cols
template <int DIN>
__global__ void k_gemm_dual(const float* __restrict__ x,
                            const float* __restrict__ Wl,
                            const float* __restrict__ Wr,
                            __nv_bfloat16* __restrict__ zlb,
                            float* __restrict__ zr, int N) {
    extern __shared__ float sm[];
    float* ws = sm;                 // DIN * 128
    float* xs = sm + DIN * 128;     // 32 * DIN
    const int tid = threadIdx.x;

    for (int i = tid; i < DIN * 128; i += 256) {
        int k = i >> 7, j = i & 127;
        ws[i] = (j < 64) ? Wl[k * 64 + j] : Wr[k * 64 + (j - 64)];
    }
    const int base = blockIdx.x * 32;
    for (int i = tid; i < 32 * DIN; i += 256) {
        int n = i / DIN, k = i % DIN;
        int node = base + n;
        xs[i] = (node < N) ? x[(long long)node * DIN + k] : 0.0f;
    }
    __syncthreads();

    const int tx = tid & 31;
    const int ty = tid >> 5;
    float acc[4][4];
#pragma unroll
    for (int a = 0; a < 4; a++)
#pragma unroll
        for (int b = 0; b < 4; b++) acc[a][b] = 0.0f;

    const float* xs0 = xs + (ty * 4) * DIN;
#pragma unroll 4
    for (int k = 0; k < DIN; k++) {
        float4 w = *(const float4*)(ws + k * 128 + tx * 4);
        float xv[4];
#pragma unroll
        for (int a = 0; a < 4; a++) xv[a] = xs0[a * DIN + k];
#pragma unroll
        for (int a = 0; a < 4; a++) {
            acc[a][0] += xv[a] * w.x;
            acc[a][1] += xv[a] * w.y;
            acc[a][2] += xv[a] * w.z;
            acc[a][3] += xv[a] * w.w;
        }
    }

    const int col = tx * 4;
#pragma unroll
    for (int a = 0; a < 4; a++) {
        int node = base + ty * 4 + a;
        if (node < N) {
            if (col < 64) {
                __nv_bfloat162 p0 = __floats2bfloat162_rn(acc[a][0], acc[a][1]);
                __nv_bfloat162 p1 = __floats2bfloat162_rn(acc[a][2], acc[a][3]);
                uint2 u;
                u.x = *(unsigned*)&p0;
                u.y = *(unsigned*)&p1;
                *(uint2*)(zlb + (long long)node * 64 + col) = u;
            } else {
                float4 v = make_float4(acc[a][0], acc[a][1], acc[a][2], acc[a][3]);
                *(float4*)(zr + (long long)node * 64 + (col - 64)) = v;
            }
        }
    }
}

// ---------------- CSR gather + combine (bf16 messages, unroll-4) ----------------
// 16 threads per node, each owns 4 cols. Pure reads, no atomics.
__global__ void k_gather(const int* __restrict__ offs, const int* __restrict__ csr,
                         const __nv_bfloat16* __restrict__ zlb, const float* __restrict__ zr,
                         const float* __restrict__ bl, float* __restrict__ h, int N) {
    int tid = threadIdx.x;
    int node = blockIdx.x * 16 + (tid >> 4);
    int c = (tid & 15) * 4;
    if (node >= N) return;
    int s0 = offs[node], s1 = offs[node + 1];
    float4 acc = make_float4(0.f, 0.f, 0.f, 0.f);
    int i = s0;
    for (; i + 4 <= s1; i += 4) {
        int sa = __ldg(csr + i);
        int sb = __ldg(csr + i + 1);
        int sc = __ldg(csr + i + 2);
        int sd = __ldg(csr + i + 3);
        uint2 ua = *(const uint2*)(zlb + (size_t)sa * 64 + c);
        uint2 ub = *(const uint2*)(zlb + (size_t)sb * 64 + c);
        uint2 uc = *(const uint2*)(zlb + (size_t)sc * 64 + c);
        uint2 ud = *(const uint2*)(zlb + (size_t)sd * 64 + c);
        float4 va = bf4_to_f4(ua);
        float4 vb = bf4_to_f4(ub);
        float4 vc = bf4_to_f4(uc);
        float4 vd = bf4_to_f4(ud);
        acc.x += (va.x + vb.x) + (vc.x + vd.x);
        acc.y += (va.y + vb.y) + (vc.y + vd.y);
        acc.z += (va.z + vb.z) + (vc.z + vd.z);
        acc.w += (va.w + vb.w) + (vc.w + vd.w);
    }
    for (; i < s1; i++) {
        int sa = __ldg(csr + i);
        float4 va = bf4_to_f4(*(const uint2*)(zlb + (size_t)sa * 64 + c));
        acc.x += va.x; acc.y += va.y; acc.z += va.z; acc.w += va.w;
    }
    float iv = 1.0f / fmaxf((float)(s1 - s0), 1.0f);
    float4 r = *(const float4*)(zr + (size_t)node * 64 + c);
    float4 b = *(const float4*)(bl + c);
    float4 o;
    o.x = acc.x * iv + r.x + b.x;
    o.y = acc.y * iv + r.y + b.y;
    o.z = acc.z * iv + r.z + b.z;
    o.w = acc.w * iv + r.w + b.w;
    *(float4*)(h + (size_t)node * 64 + c) = o;
}

// layer-3 variant: fuse global mean-pool accumulation, skip writing h
__global__ void k_gather_pool(const int* __restrict__ offs, const int* __restrict__ csr,
                              const __nv_bfloat16* __restrict__ zlb, const float* __restrict__ zr,
                              const float* __restrict__ bl, const int* __restrict__ batch,
                              float* __restrict__ pool, float* __restrict__ pcnt, int N) {
    int tid = threadIdx.x;
    int node = blockIdx.x * 16 + (tid >> 4);
    int c = (tid & 15) * 4;
    if (node >= N) return;
    int s0 = offs[node], s1 = offs[node + 1];
    float4 acc = make_float4(0.f, 0.f, 0.f, 0.f);
    int i = s0;
    for (; i + 4 <= s1; i += 4) {
        int sa = __ldg(csr + i);
        int sb = __ldg(csr + i + 1);
        int sc = __ldg(csr + i + 2);
        int sd = __ldg(csr + i + 3);
        uint2 ua = *(const uint2*)(zlb + (size_t)sa * 64 + c);
        uint2 ub = *(const uint2*)(zlb + (size_t)sb * 64 + c);
        uint2 uc = *(const uint2*)(zlb + (size_t)sc * 64 + c);
        uint2 ud = *(const uint2*)(zlb + (size_t)sd * 64 + c);
        float4 va = bf4_to_f4(ua);
        float4 vb = bf4_to_f4(ub);
        float4 vc = bf4_to_f4(uc);
        float4 vd = bf4_to_f4(ud);
        acc.x += (va.x + vb.x) + (vc.x + vd.x);
        acc.y += (va.y + vb.y) + (vc.y + vd.y);
        acc.z += (va.z + vb.z) + (vc.z + vd.z);
        acc.w += (va.w + vb.w) + (vc.w + vd.w);
    }
    for (; i < s1; i++) {
        int sa = __ldg(csr + i);
        float4 va = bf4_to_f4(*(const uint2*)(zlb + (size_t)sa * 64 + c));
        acc.x += va.x; acc.y += va.y; acc.z += va.z; acc.w += va.w;
    }
    float iv = 1.0f / fmaxf((float)(s1 - s0), 1.0f);
    float4 r = *(const float4*)(zr + (size_t)node * 64 + c);
    float4 b = *(const float4*)(bl + c);
    float4 o;
    o.x = acc.x * iv + r.x + b.x;
    o.y = acc.y * iv + r.y + b.y;
    o.z = acc.z * iv + r.z + b.z;
    o.w = acc.w * iv + r.w + b.w;
    unsigned g = (unsigned)batch[node];
    if (g < GG) {
        red_add_v4(pool + (size_t)g * 64 + c, o);
        if (c == 0) red_add_f(pcnt + g, 1.0f);
    }
}

__global__ void k_poolfin(const float* __restrict__ pool, const float* __restrict__ pcnt,
                          float* __restrict__ c0) {
    int idx = blockIdx.x * blockDim.x + threadIdx.x;
    if (idx >= GG * 64) return;
    int g = idx >> 6;
    c0[idx] = pool[idx] / fmaxf(pcnt[g], 1.0f);
}

// ---------------- fused Linear + BatchNorm(batch stats) + tanh ----------------
__global__ void k_lin_bn_tanh(const float* __restrict__ in, int din,
                              const float* __restrict__ W, const float* __restrict__ b,
                              const float* __restrict__ gamma, const float* __restrict__ beta,
                              float* __restrict__ out, int dout) {
    __shared__ float ws[256];
    __shared__ float red[256];
    const int col = blockIdx.x;
    const int tid = threadIdx.x;
    if (tid < din) ws[tid] = W[tid * dout + col];
    __syncthreads();

    float val = b[col];
    const float* row = in + tid * din;
    for (int k = 0; k < din; k++) val += row[k] * ws[k];

    red[tid] = val;
    __syncthreads();
    for (int s = 128; s > 0; s >>= 1) {
        if (tid < s) red[tid] += red[tid + s];
        __syncthreads();
    }
    float mean = red[0] * (1.0f / 256.0f);
    __syncthreads();

    float dv = val - mean;
    red[tid] = dv * dv;
    __syncthreads();
    for (int s = 128; s > 0; s >>= 1) {
        if (tid < s) red[tid] += red[tid + s];
        __syncthreads();
    }
    float var = red[0] * (1.0f / 256.0f);

    float y = dv * rsqrtf(var + 1e-5f) * gamma[col] + beta[col];
    out[tid * dout + col] = tanhf(y);
}

// ---------------- final linear 64 -> 10 ----------------
__global__ void k_final(const float* __restrict__ in, const float* __restrict__ W,
                        const float* __restrict__ b, float* __restrict__ out) {
    __shared__ float ws[64 * 10];
    __shared__ float bs[10];
    const int tid = threadIdx.x;
    for (int i = tid; i < 640; i += 256) ws[i] = W[i];
    if (tid < 10) bs[tid] = b[tid];
    __syncthreads();
    float acc[10];
#pragma unroll
    for (int j = 0; j < 10; j++) acc[j] = bs[j];
    const float* row = in + tid * 64;
    for (int k = 0; k < 64; k++) {
        float xv = row[k];
#pragma unroll
        for (int j = 0; j < 10; j++) acc[j] += xv * ws[k * 10 + j];
    }
#pragma unroll
    for (int j = 0; j < 10; j++) out[tid * 10 + j] = acc[j];
}

// ---------------- launch ----------------
extern "C" void kernel_launch(void* const* d_in, const int* in_sizes, int n_in,
                              void* d_out, int out_size) {
    const float* x = (const float*)d_in[0];
    const int* ei = (const int*)d_in[1];
    const int* batch = (const int*)d_in[2];
    const float* W1l = (const float*)d_in[3];
    const float* b1l = (const float*)d_in[4];
    const float* W1r = (const float*)d_in[5];
    const float* W2l = (const float*)d_in[6];
    const float* b2l = (const float*)d_in[7];
    const float* W2r = (const float*)d_in[8];
    const float* W3l = (const float*)d_in[9];
    const float* b3l = (const float*)d_in[10];
    const float* W3r = (const float*)d_in[11];
    const float* lin1_w = (const float*)d_in[12];
    const float* lin1_b = (const float*)d_in[13];
    const float* g1 = (const float*)d_in[14];
    const float* be1 = (const float*)d_in[15];
    const float* lin2_w = (const float*)d_in[16];
    const float* lin2_b = (const float*)d_in[17];
    const float* g2 = (const float*)d_in[18];
    const float* be2 = (const float*)d_in[19];
    const float* lin3_w = (const float*)d_in[20];
    const float* lin3_b = (const float*)d_in[21];
    const float* g3 = (const float*)d_in[22];
    const float* be3 = (const float*)d_in[23];
    const float* lin4_w = (const float*)d_in[24];
    const float* lin4_b = (const float*)d_in[25];

    const int N = in_sizes[0] / INW;   // 50000
    const int E = in_sizes[1] / 2;     // 800000
    const int* src = ei;
    const int* dst = ei + E;

    float *zr, *h, *pool, *pcnt, *cA, *cB;
    __nv_bfloat16* zlb;
    int *cnt, *offs, *cursor, *csr, *bsum;
    cudaGetSymbolAddress((void**)&zlb, g_zlb);
    cudaGetSymbolAddress((void**)&zr, g_zr);
    cudaGetSymbolAddress((void**)&h, g_h);
    cudaGetSymbolAddress((void**)&cnt, g_cnt);
    cudaGetSymbolAddress((void**)&offs, g_offs);
    cudaGetSymbolAddress((void**)&cursor, g_cursor);
    cudaGetSymbolAddress((void**)&csr, g_csr);
    cudaGetSymbolAddress((void**)&bsum, g_bsum);
    cudaGetSymbolAddress((void**)&pool, g_pool);
    cudaGetSymbolAddress((void**)&pcnt, g_pcnt);
    cudaGetSymbolAddress((void**)&cA, g_cA);
    cudaGetSymbolAddress((void**)&cB, g_cB);

    const int SMEM1 = (INW * 128 + 32 * INW) * 4;   // 81920
    const int SMEM2 = (64 * 128 + 32 * 64) * 4;     // 40960
    cudaFuncSetAttribute(k_gemm_dual<128>, cudaFuncAttributeMaxDynamicSharedMemorySize, SMEM1);
    cudaFuncSetAttribute(k_gemm_dual<64>, cudaFuncAttributeMaxDynamicSharedMemorySize, SMEM2);

    const int gemm_blocks = (N + 31) / 32;
    const int gat_blocks = (N + 15) / 16;

    // ---- CSR build (once, reused by all 3 layers) ----
    cudaMemsetAsync(cnt, 0, (size_t)N * sizeof(int), 0);
    k_count<<<(E + 255) / 256, 256>>>(dst, cnt, E);
    k_scan1<<<NBLK, SCAN_BLK>>>(cnt, offs, bsum, N);
    k_scan2<<<1, 128>>>(bsum, NBLK);
    k_scan3<<<(N + 255) / 256, 256>>>(offs, bsum, cursor, N, E);
    k_fill<<<(E + 255) / 256, 256>>>(src, dst, cursor, csr, E);

    // ---- layer 1 ----
    k_gemm_dual<128><<<gemm_blocks, 256, SMEM1>>>(x, W1l, W1r, zlb, zr, N);
    k_gather<<<gat_blocks, 256>>>(offs, csr, zlb, zr, b1l, h, N);

    // ---- layer 2 ----
    k_gemm_dual<64><<<gemm_blocks, 256, SMEM2>>>(h, W2l, W2r, zlb, zr, N);
    k_gather<<<gat_blocks, 256>>>(offs, csr, zlb, zr, b2l, h, N);

    // ---- layer 3 + fused global mean pool ----
    k_gemm_dual<64><<<gemm_blocks, 256, SMEM2>>>(h, W3l, W3r, zlb, zr, N);
    cudaMemsetAsync(pool, 0, (size_t)GG * 64 * sizeof(float), 0);
    cudaMemsetAsync(pcnt, 0, (size_t)GG * sizeof(float), 0);
    k_gather_pool<<<gat_blocks, 256>>>(offs, csr, zlb, zr, b3l, batch, pool, pcnt, N);
    k_poolfin<<<(GG * 64 + 255) / 256, 256>>>(pool, pcnt, cA);

    // ---- MLP head ----
    k_lin_bn_tanh<<<256, 256>>>(cA, 64, lin1_w, lin1_b, g1, be1, cB, 256);
    k_lin_bn_tanh<<<128, 256>>>(cB, 256, lin2_w, lin2_b, g2, be2, cA, 128);
    k_lin_bn_tanh<<<64, 256>>>(cA, 128, lin3_w, lin3_b, g3, be3, cB, 64);
    k_final<<<1, 256>>>(cB, lin4_w, lin4_b, (float*)d_out);
}

// round 14
// speedup vs baseline: 1.7738x; 1.1313x over previous
#include <cuda_runtime.h>
#include <cuda_fp16.h>
#include <cstdint>

// ---------------- problem constants ----------------
#define NN 50000
#define EE 800000
#define GG 256
#define HH 64
#define INW 128
#define SCAN_BLK 512
#define NBLK ((NN + SCAN_BLK - 1) / SCAN_BLK)   // 98

// ---------------- device scratch (no allocation allowed) ----------------
__device__ __half g_zlh[NN * HH];   // messages in fp16 (half gather traffic, 8x less noise than bf16)
__device__ float g_zr[NN * HH];
__device__ float g_h[NN * HH];
__device__ int   g_cnt[NN];
__device__ int   g_offs[NN + 1];
__device__ int   g_cursor[NN];
__device__ int   g_csr[EE];
__device__ int   g_bsum[128];
__device__ float g_pool[GG * HH];
__device__ float g_pcnt[GG];
__device__ float g_cA[GG * 256];
__device__ float g_cB[GG * 256];

// ---------------- helpers ----------------
__device__ __forceinline__ void red_add_v4(float* a, float4 v) {
    asm volatile("red.global.add.v4.f32 [%0], {%1,%2,%3,%4};"
                 :: "l"(a), "f"(v.x), "f"(v.y), "f"(v.z), "f"(v.w) : "memory");
}
__device__ __forceinline__ void red_add_f(float* a, float v) {
    asm volatile("red.global.add.f32 [%0], %1;" :: "l"(a), "f"(v) : "memory");
}
// packed dual-fp32 FMA (FFMA2): d = a*b + d  (two fp32 lanes, PTX-only)
__device__ __forceinline__ void ffma2(unsigned long long& d,
                                      unsigned long long a, unsigned long long b) {
    asm("fma.rn.f32x2 %0, %1, %2, %0;" : "+l"(d) : "l"(a), "l"(b));
}
__device__ __forceinline__ unsigned long long pack2(float v) {
    unsigned long long r;
    asm("mov.b64 %0, {%1, %1};" : "=l"(r) : "f"(v));
    return r;
}
__device__ __forceinline__ float4 hf4_to_f4(uint2 u) {
    __half2 p0 = *(__half2*)&u.x;
    __half2 p1 = *(__half2*)&u.y;
    float2 a = __half22float2(p0);
    float2 b = __half22float2(p1);
    return make_float4(a.x, a.y, b.x, b.y);
}

// ---------------- CSR build ----------------
__global__ void k_count(const int* __restrict__ dst, int* __restrict__ cnt, int E) {
    int e = blockIdx.x * blockDim.x + threadIdx.x;
    if (e >= E) return;
    unsigned d = (unsigned)dst[e];
    if (d < NN) atomicAdd(cnt + d, 1);
}

__global__ void k_scan1(const int* __restrict__ cnt, int* __restrict__ offs,
                        int* __restrict__ bsum, int N) {
    __shared__ int sh[SCAN_BLK];
    int i = blockIdx.x * SCAN_BLK + threadIdx.x;
    int v = (i < N) ? cnt[i] : 0;
    sh[threadIdx.x] = v;
    __syncthreads();
    for (int d = 1; d < SCAN_BLK; d <<= 1) {
        int t = (threadIdx.x >= d) ? sh[threadIdx.x - d] : 0;
        __syncthreads();
        sh[threadIdx.x] += t;
        __syncthreads();
    }
    if (i < N) offs[i] = sh[threadIdx.x] - v;   // exclusive
    if (threadIdx.x == SCAN_BLK - 1) bsum[blockIdx.x] = sh[SCAN_BLK - 1];
}

__global__ void k_scan2(int* __restrict__ bsum, int nb) {
    __shared__ int sh[128];
    int v = (threadIdx.x < nb) ? bsum[threadIdx.x] : 0;
    sh[threadIdx.x] = v;
    __syncthreads();
    for (int d = 1; d < 128; d <<= 1) {
        int t = (threadIdx.x >= d) ? sh[threadIdx.x - d] : 0;
        __syncthreads();
        sh[threadIdx.x] += t;
        __syncthreads();
    }
    if (threadIdx.x < nb) bsum[threadIdx.x] = sh[threadIdx.x] - v;   // exclusive
}

__global__ void k_scan3(int* __restrict__ offs, const int* __restrict__ bsum,
                        int* __restrict__ cursor, int N, int E) {
    int i = blockIdx.x * blockDim.x + threadIdx.x;
    if (i < N) {
        int o = offs[i] + bsum[i / SCAN_BLK];
        offs[i] = o;
        cursor[i] = o;
    }
    if (i == 0) offs[N] = E;
}

__global__ void k_fill(const int* __restrict__ src, const int* __restrict__ dst,
                       int* __restrict__ cursor, int* __restrict__ csr, int E) {
    int e = blockIdx.x * blockDim.x + threadIdx.x;
    if (e >= E) return;
    unsigned s = (unsigned)src[e];
    unsigned d = (unsigned)dst[e];
    if (s >= NN || d >= NN) return;
    int pos = atomicAdd(cursor + d, 1);
    csr[pos] = (int)s;
}

// ---------------- dual GEMM via FFMA2: zl(fp16) = x @ Wl, zr(f32) = x @ Wr ----------------
// block = 256 threads (8 warps); tile = 64 nodes x 128 cols.
// Per warp: 32 lanes own 4 cols each (one LDS.128 of w per k), 8 nodes per warp
// (x values are warp-uniform broadcasts). 16 FFMA2 per warp-k amortize one w-load.
template <int DIN>
__global__ void k_gemm_dual(const float* __restrict__ x,
                            const float* __restrict__ Wl,
                            const float* __restrict__ Wr,
                            __half* __restrict__ zlh,
                            float* __restrict__ zr, int N) {
    extern __shared__ float sm[];
    float* ws = sm;                 // DIN * 128
    float* xs = sm + DIN * 128;     // 64 * DIN (node-major)
    const int tid = threadIdx.x;

    for (int i = tid; i < DIN * 128; i += 256) {
        int k = i >> 7, j = i & 127;
        ws[i] = (j < 64) ? Wl[k * 64 + j] : Wr[k * 64 + (j - 64)];
    }
    const int base = blockIdx.x * 64;
    constexpr int KQ = DIN / 4;
    for (int i = tid; i < 64 * KQ; i += 256) {
        int n = i / KQ, kq = i % KQ;
        int node = base + n;
        float4 v = (node < N) ? *(const float4*)(x + (size_t)node * DIN + kq * 4)
                              : make_float4(0.f, 0.f, 0.f, 0.f);
        *(float4*)(xs + n * DIN + kq * 4) = v;
    }
    __syncthreads();

    const int tx = tid & 31;   // lane -> cols [4*tx, 4*tx+4)
    const int wy = tid >> 5;   // warp -> nodes [base+8*wy, base+8*wy+8)

    unsigned long long acc[8][2];
#pragma unroll
    for (int a = 0; a < 8; a++) { acc[a][0] = 0ull; acc[a][1] = 0ull; }

    const float* xs0 = xs + (wy * 8) * DIN;
#pragma unroll 4
    for (int k = 0; k < DIN; k++) {
        ulonglong2 w2 = *(const ulonglong2*)(ws + k * 128 + tx * 4);
#pragma unroll
        for (int a = 0; a < 8; a++) {
            unsigned long long xp = pack2(xs0[a * DIN + k]);
            ffma2(acc[a][0], xp, w2.x);
            ffma2(acc[a][1], xp, w2.y);
        }
    }

    const int col = tx * 4;
#pragma unroll
    for (int a = 0; a < 8; a++) {
        int node = base + wy * 8 + a;
        if (node >= N) continue;
        float2 p0 = *(float2*)&acc[a][0];
        float2 p1 = *(float2*)&acc[a][1];
        if (col < 64) {
            __half2 h0 = __floats2half2_rn(p0.x, p0.y);
            __half2 h1 = __floats2half2_rn(p1.x, p1.y);
            uint2 u;
            u.x = *(unsigned*)&h0;
            u.y = *(unsigned*)&h1;
            *(uint2*)(zlh + (size_t)node * 64 + col) = u;
        } else {
            float4 v = make_float4(p0.x, p0.y, p1.x, p1.y);
            *(float4*)(zr + (size_t)node * 64 + (col - 64)) = v;
        }
    }
}

// ---------------- CSR gather + combine (fp16 messages, unroll-4) ----------------
__global__ void k_gather(const int* __restrict__ offs, const int* __restrict__ csr,
                         const __half* __restrict__ zlh, const float* __restrict__ zr,
                         const float* __restrict__ bl, float* __restrict__ h, int N) {
    int tid = threadIdx.x;
    int node = blockIdx.x * 16 + (tid >> 4);
    int c = (tid & 15) * 4;
    if (node >= N) return;
    int s0 = offs[node], s1 = offs[node + 1];
    float4 acc = make_float4(0.f, 0.f, 0.f, 0.f);
    int i = s0;
    for (; i + 4 <= s1; i += 4) {
        int sa = __ldg(csr + i);
        int sb = __ldg(csr + i + 1);
        int sc = __ldg(csr + i + 2);
        int sd = __ldg(csr + i + 3);
        float4 va = hf4_to_f4(*(const uint2*)(zlh + (size_t)sa * 64 + c));
        float4 vb = hf4_to_f4(*(const uint2*)(zlh + (size_t)sb * 64 + c));
        float4 vc = hf4_to_f4(*(const uint2*)(zlh + (size_t)sc * 64 + c));
        float4 vd = hf4_to_f4(*(const uint2*)(zlh + (size_t)sd * 64 + c));
        acc.x += (va.x + vb.x) + (vc.x + vd.x);
        acc.y += (va.y + vb.y) + (vc.y + vd.y);
        acc.z += (va.z + vb.z) + (vc.z + vd.z);
        acc.w += (va.w + vb.w) + (vc.w + vd.w);
    }
    for (; i < s1; i++) {
        int sa = __ldg(csr + i);
        float4 va = hf4_to_f4(*(const uint2*)(zlh + (size_t)sa * 64 + c));
        acc.x += va.x; acc.y += va.y; acc.z += va.z; acc.w += va.w;
    }
    float iv = 1.0f / fmaxf((float)(s1 - s0), 1.0f);
    float4 r = *(const float4*)(zr + (size_t)node * 64 + c);
    float4 b = *(const float4*)(bl + c);
    float4 o;
    o.x = acc.x * iv + r.x + b.x;
    o.y = acc.y * iv + r.y + b.y;
    o.z = acc.z * iv + r.z + b.z;
    o.w = acc.w * iv + r.w + b.w;
    *(float4*)(h + (size_t)node * 64 + c) = o;
}

// layer-3 variant: fuse global mean-pool accumulation, skip writing h
__global__ void k_gather_pool(const int* __restrict__ offs, const int* __restrict__ csr,
                              const __half* __restrict__ zlh, const float* __restrict__ zr,
                              const float* __restrict__ bl, const int* __restrict__ batch,
                              float* __restrict__ pool, float* __restrict__ pcnt, int N) {
    int tid = threadIdx.x;
    int node = blockIdx.x * 16 + (tid >> 4);
    int c = (tid & 15) * 4;
    if (node >= N) return;
    int s0 = offs[node], s1 = offs[node + 1];
    float4 acc = make_float4(0.f, 0.f, 0.f, 0.f);
    int i = s0;
    for (; i + 4 <= s1; i += 4) {
        int sa = __ldg(csr + i);
        int sb = __ldg(csr + i + 1);
        int sc = __ldg(csr + i + 2);
        int sd = __ldg(csr + i + 3);
        float4 va = hf4_to_f4(*(const uint2*)(zlh + (size_t)sa * 64 + c));
        float4 vb = hf4_to_f4(*(const uint2*)(zlh + (size_t)sb * 64 + c));
        float4 vc = hf4_to_f4(*(const uint2*)(zlh + (size_t)sc * 64 + c));
        float4 vd = hf4_to_f4(*(const uint2*)(zlh + (size_t)sd * 64 + c));
        acc.x += (va.x + vb.x) + (vc.x + vd.x);
        acc.y += (va.y + vb.y) + (vc.y + vd.y);
        acc.z += (va.z + vb.z) + (vc.z + vd.z);
        acc.w += (va.w + vb.w) + (vc.w + vd.w);
    }
    for (; i < s1; i++) {
        int sa = __ldg(csr + i);
        float4 va = hf4_to_f4(*(const uint2*)(zlh + (size_t)sa * 64 + c));
        acc.x += va.x; acc.y += va.y; acc.z += va.z; acc.w += va.w;
    }
    float iv = 1.0f / fmaxf((float)(s1 - s0), 1.0f);
    float4 r = *(const float4*)(zr + (size_t)node * 64 + c);
    float4 b = *(const float4*)(bl + c);
    float4 o;
    o.x = acc.x * iv + r.x + b.x;
    o.y = acc.y * iv + r.y + b.y;
    o.z = acc.z * iv + r.z + b.z;
    o.w = acc.w * iv + r.w + b.w;
    unsigned g = (unsigned)batch[node];
    if (g < GG) {
        red_add_v4(pool + (size_t)g * 64 + c, o);
        if (c == 0) red_add_f(pcnt + g, 1.0f);
    }
}

__global__ void k_poolfin(const float* __restrict__ pool, const float* __restrict__ pcnt,
                          float* __restrict__ c0) {
    int idx = blockIdx.x * blockDim.x + threadIdx.x;
    if (idx >= GG * 64) return;
    int g = idx >> 6;
    c0[idx] = pool[idx] / fmaxf(pcnt[g], 1.0f);
}

// ---------------- fused Linear + BatchNorm(batch stats) + tanh ----------------
__global__ void k_lin_bn_tanh(const float* __restrict__ in, int din,
                              const float* __restrict__ W, const float* __restrict__ b,
                              const float* __restrict__ gamma, const float* __restrict__ beta,
                              float* __restrict__ out, int dout) {
    __shared__ float ws[256];
    __shared__ float red[256];
    const int col = blockIdx.x;
    const int tid = threadIdx.x;
    if (tid < din) ws[tid] = W[tid * dout + col];
    __syncthreads();

    float val = b[col];
    const float* row = in + tid * din;
    for (int k = 0; k < din; k++) val += row[k] * ws[k];

    red[tid] = val;
    __syncthreads();
    for (int s = 128; s > 0; s >>= 1) {
        if (tid < s) red[tid] += red[tid + s];
        __syncthreads();
    }
    float mean = red[0] * (1.0f / 256.0f);
    __syncthreads();

    float dv = val - mean;
    red[tid] = dv * dv;
    __syncthreads();
    for (int s = 128; s > 0; s >>= 1) {
        if (tid < s) red[tid] += red[tid + s];
        __syncthreads();
    }
    float var = red[0] * (1.0f / 256.0f);

    float y = dv * rsqrtf(var + 1e-5f) * gamma[col] + beta[col];
    out[tid * dout + col] = tanhf(y);
}

// ---------------- final linear 64 -> 10 ----------------
__global__ void k_final(const float* __restrict__ in, const float* __restrict__ W,
                        const float* __restrict__ b, float* __restrict__ out) {
    __shared__ float ws[64 * 10];
    __shared__ float bs[10];
    const int tid = threadIdx.x;
    for (int i = tid; i < 640; i += 256) ws[i] = W[i];
    if (tid < 10) bs[tid] = b[tid];
    __syncthreads();
    float acc[10];
#pragma unroll
    for (int j = 0; j < 10; j++) acc[j] = bs[j];
    const float* row = in + tid * 64;
    for (int k = 0; k < 64; k++) {
        float xv = row[k];
#pragma unroll
        for (int j = 0; j < 10; j++) acc[j] += xv * ws[k * 10 + j];
    }
#pragma unroll
    for (int j = 0; j < 10; j++) out[tid * 10 + j] = acc[j];
}

// ---------------- launch ----------------
extern "C" void kernel_launch(void* const* d_in, const int* in_sizes, int n_in,
                              void* d_out, int out_size) {
    const float* x = (const float*)d_in[0];
    const int* ei = (const int*)d_in[1];
    const int* batch = (const int*)d_in[2];
    const float* W1l = (const float*)d_in[3];
    const float* b1l = (const float*)d_in[4];
    const float* W1r = (const float*)d_in[5];
    const float* W2l = (const float*)d_in[6];
    const float* b2l = (const float*)d_in[7];
    const float* W2r = (const float*)d_in[8];
    const float* W3l = (const float*)d_in[9];
    const float* b3l = (const float*)d_in[10];
    const float* W3r = (const float*)d_in[11];
    const float* lin1_w = (const float*)d_in[12];
    const float* lin1_b = (const float*)d_in[13];
    const float* g1 = (const float*)d_in[14];
    const float* be1 = (const float*)d_in[15];
    const float* lin2_w = (const float*)d_in[16];
    const float* lin2_b = (const float*)d_in[17];
    const float* g2 = (const float*)d_in[18];
    const float* be2 = (const float*)d_in[19];
    const float* lin3_w = (const float*)d_in[20];
    const float* lin3_b = (const float*)d_in[21];
    const float* g3 = (const float*)d_in[22];
    const float* be3 = (const float*)d_in[23];
    const float* lin4_w = (const float*)d_in[24];
    const float* lin4_b = (const float*)d_in[25];

    const int N = in_sizes[0] / INW;   // 50000
    const int E = in_sizes[1] / 2;     // 800000
    const int* src = ei;
    const int* dst = ei + E;

    float *zr, *h, *pool, *pcnt, *cA, *cB;
    __half* zlh;
    int *cnt, *offs, *cursor, *csr, *bsum;
    cudaGetSymbolAddress((void**)&zlh, g_zlh);
    cudaGetSymbolAddress((void**)&zr, g_zr);
    cudaGetSymbolAddress((void**)&h, g_h);
    cudaGetSymbolAddress((void**)&cnt, g_cnt);
    cudaGetSymbolAddress((void**)&offs, g_offs);
    cudaGetSymbolAddress((void**)&cursor, g_cursor);
    cudaGetSymbolAddress((void**)&csr, g_csr);
    cudaGetSymbolAddress((void**)&bsum, g_bsum);
    cudaGetSymbolAddress((void**)&pool, g_pool);
    cudaGetSymbolAddress((void**)&pcnt, g_pcnt);
    cudaGetSymbolAddress((void**)&cA, g_cA);
    cudaGetSymbolAddress((void**)&cB, g_cB);

    const int SMEM1 = (INW * 128 + 64 * INW) * 4;   // 98304
    const int SMEM2 = (64 * 128 + 64 * 64) * 4;     // 49152
    cudaFuncSetAttribute(k_gemm_dual<128>, cudaFuncAttributeMaxDynamicSharedMemorySize, SMEM1);
    cudaFuncSetAttribute(k_gemm_dual<64>, cudaFuncAttributeMaxDynamicSharedMemorySize, SMEM2);

    const int gemm_blocks = (N + 63) / 64;
    const int gat_blocks = (N + 15) / 16;

    // ---- CSR build (once, reused by all 3 layers) ----
    cudaMemsetAsync(cnt, 0, (size_t)N * sizeof(int), 0);
    k_count<<<(E + 255) / 256, 256>>>(dst, cnt, E);
    k_scan1<<<NBLK, SCAN_BLK>>>(cnt, offs, bsum, N);
    k_scan2<<<1, 128>>>(bsum, NBLK);
    k_scan3<<<(N + 255) / 256, 256>>>(offs, bsum, cursor, N, E);
    k_fill<<<(E + 255) / 256, 256>>>(src, dst, cursor, csr, E);

    // ---- layer 1 ----
    k_gemm_dual<128><<<gemm_blocks, 256, SMEM1>>>(x, W1l, W1r, zlh, zr, N);
    k_gather<<<gat_blocks, 256>>>(offs, csr, zlh, zr, b1l, h, N);

    // ---- layer 2 ----
    k_gemm_dual<64><<<gemm_blocks, 256, SMEM2>>>(h, W2l, W2r, zlh, zr, N);
    k_gather<<<gat_blocks, 256>>>(offs, csr, zlh, zr, b2l, h, N);

    // ---- layer 3 + fused global mean pool ----
    k_gemm_dual<64><<<gemm_blocks, 256, SMEM2>>>(h, W3l, W3r, zlh, zr, N);
    cudaMemsetAsync(pool, 0, (size_t)GG * 64 * sizeof(float), 0);
    cudaMemsetAsync(pcnt, 0, (size_t)GG * sizeof(float), 0);
    k_gather_pool<<<gat_blocks, 256>>>(offs, csr, zlh, zr, b3l, batch, pool, pcnt, N);
    k_poolfin<<<(GG * 64 + 255) / 256, 256>>>(pool, pcnt, cA);

    // ---- MLP head ----
    k_lin_bn_tanh<<<256, 256>>>(cA, 64, lin1_w, lin1_b, g1, be1, cB, 256);
    k_lin_bn_tanh<<<128, 256>>>(cB, 256, lin2_w, lin2_b, g2, be2, cA, 128);
    k_lin_bn_tanh<<<64, 256>>>(cA, 128, lin3_w, lin3_b, g3, be3, cB, 64);
    k_final<<<1, 256>>>(cB, lin4_w, lin4_b, (float*)d_out);
}